// round 9
// baseline (speedup 1.0000x reference)
#include <cuda_runtime.h>
#include <cuda_bf16.h>
#include <cstdint>
#include <math.h>

#define BB 32768
#define EE 16
#define MM 64
#define DD 256
#define RT 256
#define NT 512

#define O_W ((size_t)0)
#define O_S ((size_t)BB)
#define O_Y ((size_t)(2*BB))
#define O_G (O_Y + (size_t)BB*EE*DD)
#define O_A (O_G + (size_t)BB*EE)

// preconverted operands + scratch
__device__ __nv_bfloat16 g_Khi[EE*MM*DD];
__device__ __nv_bfloat16 g_Klo[EE*MM*DD];
__device__ __nv_bfloat16 g_Vthi[EE*DD*MM];   // [E][D][M]
__device__ __nv_bfloat16 g_Vtlo[EE*DD*MM];
__device__ __nv_bfloat16 g_wghi[EE*DD];
__device__ __nv_bfloat16 g_wglo[EE*DD];
__device__ float g_px[(size_t)BB*EE];
__device__ float g_pn[(size_t)BB*EE];
__device__ float g_xn[BB];

// smem: x_lo tile [256 rows][512B] swizzled + K/V hi/lo buffers
#define S_XLO 0        // 131072
#define S_B0  131072   // 32768: K_hi / Vt_hi (wg_hi in prologue)
#define S_B1  163840   // 32768: K_lo / Vt_lo (wg_lo)
#define SMEM_REQ 196608

__device__ __forceinline__ uint32_t smem_u32(const void* p) {
    uint32_t a;
    asm("{ .reg .u64 t; cvta.to.shared.u64 t, %1; cvt.u32.u64 %0, t; }" : "=r"(a) : "l"(p));
    return a;
}
__device__ __forceinline__ void ldsm4(uint32_t* r, uint32_t addr) {
    asm volatile("ldmatrix.sync.aligned.m8n8.x4.shared.b16 {%0,%1,%2,%3}, [%4];"
        : "=r"(r[0]), "=r"(r[1]), "=r"(r[2]), "=r"(r[3]) : "r"(addr));
}
__device__ __forceinline__ void mma_bf16(float* c, const uint32_t* a, const uint32_t* b) {
    asm volatile("mma.sync.aligned.m16n8k16.row.col.f32.bf16.bf16.f32 "
        "{%0,%1,%2,%3}, {%4,%5,%6,%7}, {%8,%9}, {%0,%1,%2,%3};"
        : "+f"(c[0]), "+f"(c[1]), "+f"(c[2]), "+f"(c[3])
        : "r"(a[0]), "r"(a[1]), "r"(a[2]), "r"(a[3]), "r"(b[0]), "r"(b[1]));
}
__device__ __forceinline__ void cpasync16(uint32_t dst, const void* src) {
    asm volatile("cp.async.cg.shared.global [%0], [%1], 16;" :: "r"(dst), "l"(src));
}
#define CP_COMMIT() asm volatile("cp.async.commit_group;" ::: "memory")
#define CP_WAIT0()  asm volatile("cp.async.wait_group 0;" ::: "memory")

__device__ __forceinline__ uint32_t addrA(uint32_t base, int r0, int c0, int rb, int lane) {
    int row = r0 + (lane & 15);
    int c = c0 + (lane >> 4);
    return base + row * rb + ((c ^ (row & 7)) << 4);
}
__device__ __forceinline__ uint32_t addrB(uint32_t base, int n0, int c0, int rb, int lane) {
    int row = n0 + ((lane >> 4) << 3) + (lane & 7);
    int c = c0 + ((lane >> 3) & 1);
    return base + row * rb + ((c ^ (row & 7)) << 4);
}
__device__ __forceinline__ uint32_t pack2(__nv_bfloat16 a, __nv_bfloat16 b) {
    return ((uint32_t)__bfloat16_as_ushort(b) << 16) | (uint32_t)__bfloat16_as_ushort(a);
}
__device__ __forceinline__ void split_bf(float v, __nv_bfloat16& h, __nv_bfloat16& l) {
    h = __float2bfloat16(v);
    l = __float2bfloat16(v - __bfloat162float(h));
}
__device__ __forceinline__ uint32_t packhi2(float a, float b) {
    return pack2(__float2bfloat16(a), __float2bfloat16(b));
}
__device__ __forceinline__ uint32_t packlo2(float a, float b) {
    __nv_bfloat16 ha = __float2bfloat16(a), hb = __float2bfloat16(b);
    return pack2(__float2bfloat16(a - __bfloat162float(ha)),
                 __float2bfloat16(b - __bfloat162float(hb)));
}

// ---------------- preprocess ----------------
__global__ void pp_kernel(const float* __restrict__ K, const float* __restrict__ V,
                          const float* __restrict__ wg) {
    const int total = EE * MM * DD;
    for (int idx = blockIdx.x * blockDim.x + threadIdx.x; idx < total;
         idx += gridDim.x * blockDim.x) {
        __nv_bfloat16 h, l;
        split_bf(K[idx], h, l);
        g_Khi[idx] = h; g_Klo[idx] = l;
        int e = idx >> 14, rem = idx & 16383, d = rem >> 6, m = rem & 63;
        split_bf(V[(e << 14) + m * DD + d], h, l);
        g_Vthi[idx] = h; g_Vtlo[idx] = l;
        if (idx < EE * DD) { split_bf(wg[idx], h, l); g_wghi[idx] = h; g_wglo[idx] = l; }
    }
}

// ================= main fused kernel =================
__global__ __launch_bounds__(NT, 1) void more_mma(
    const float* __restrict__ x, const float* __restrict__ bg,
    float* __restrict__ out)
{
    extern __shared__ char smem[];
    const uint32_t sb = smem_u32(smem);

    const int tid  = threadIdx.x;
    const int warp = tid >> 5;
    const int lane = tid & 31;
    const int gid  = lane >> 2;
    const int tig  = lane & 3;
    const int rb   = blockIdx.x * RT;
    const int rowA = 16 * warp + gid;      // 0..255
    const int rowB = rowA + 8;

    // ---- prologue: x_lo -> smem swizzled tile; x_hi -> persistent A-frag regs ----
    #pragma unroll 4
    for (int i = 0; i < 32; i++) {
        int f4i = i * NT + tid;
        int r = f4i >> 6, c4 = f4i & 63;
        float4 v = *(const float4*)&x[(size_t)(rb + r) * DD + c4 * 4];
        __nv_bfloat16 h0,h1,h2,h3,l0,l1,l2,l3;
        split_bf(v.x,h0,l0); split_bf(v.y,h1,l1); split_bf(v.z,h2,l2); split_bf(v.w,h3,l3);
        int o = r * 512 + ((((c4 >> 1) ^ (r & 7))) << 4) + (c4 & 1) * 8;
        *(uint2*)(smem + S_XLO + o) = make_uint2(pack2(l0,l1), pack2(l2,l3));
    }
    // x_hi fragments: 16 k-chunks x 4 regs (persistent across all experts)
    uint32_t xh[64];
    {
        const float* xpA = &x[(size_t)(rb + rowA) * DD + 2 * tig];
        const float* xpB = &x[(size_t)(rb + rowB) * DD + 2 * tig];
        #pragma unroll
        for (int ks = 0; ks < 16; ks++) {
            float2 g0 = *(const float2*)&xpA[16 * ks];
            float2 g1 = *(const float2*)&xpB[16 * ks];
            float2 g2 = *(const float2*)&xpA[16 * ks + 8];
            float2 g3 = *(const float2*)&xpB[16 * ks + 8];
            xh[4*ks+0] = packhi2(g0.x, g0.y);
            xh[4*ks+1] = packhi2(g1.x, g1.y);
            xh[4*ks+2] = packhi2(g2.x, g2.y);
            xh[4*ks+3] = packhi2(g3.x, g3.y);
        }
    }
    // wg hi -> B0, lo -> B1 (16 rows x 512B = 512 uint4)
    {
        const uint4* Wh = (const uint4*)g_wghi;
        const uint4* Wl = (const uint4*)g_wglo;
        int row = tid >> 5, c = tid & 31;
        int o = row * 512 + ((c ^ (row & 7)) << 4);
        *(uint4*)(smem + S_B0 + o) = Wh[tid];
        *(uint4*)(smem + S_B1 + o) = Wl[tid];
    }
    // x row norms
    if (tid < RT) {
        const float4* xr = (const float4*)&x[(size_t)(rb + tid) * DD];
        float s = 0.f;
        #pragma unroll 8
        for (int j = 0; j < 64; j++) {
            float4 v = xr[j];
            s = fmaf(v.x, v.x, fmaf(v.y, v.y, fmaf(v.z, v.z, fmaf(v.w, v.w, s))));
        }
        g_xn[rb + tid] = sqrtf(s);
    }
    __syncthreads();

    // ---- gate GEMM: full N=16 per warp, 3-term ----
    {
        float accg[2][4] = {};
        uint32_t al[4], bh[4], bl[4];
        #pragma unroll 2
        for (int ks = 0; ks < 16; ks++) {
            ldsm4(al, addrA(sb + S_XLO, 16 * warp, 2 * ks, 512, lane));
            ldsm4(bh, addrB(sb + S_B0, 0, 2 * ks, 512, lane));
            ldsm4(bl, addrB(sb + S_B1, 0, 2 * ks, 512, lane));
            const uint32_t* ah = xh + 4 * ks;
            mma_bf16(accg[0], ah, bh); mma_bf16(accg[1], ah, bh + 2);
            mma_bf16(accg[0], al, bh); mma_bf16(accg[1], al, bh + 2);
            mma_bf16(accg[0], ah, bl); mma_bf16(accg[1], ah, bl + 2);
        }
        __syncthreads();    // wg reads done -> B0/B1 reusable
        // sigmoid + direct store from fragments (cols 8t+2tig)
        #pragma unroll
        for (int t = 0; t < 2; t++) {
            float zA0 = accg[t][0] + bg[8*t + 2*tig];
            float zA1 = accg[t][1] + bg[8*t + 2*tig + 1];
            float zB0 = accg[t][2] + bg[8*t + 2*tig];
            float zB1 = accg[t][3] + bg[8*t + 2*tig + 1];
            *(float2*)&out[O_G + (size_t)(rb + rowA) * EE + 8*t + 2*tig] =
                make_float2(1.f/(1.f+__expf(-zA0)), 1.f/(1.f+__expf(-zA1)));
            *(float2*)&out[O_G + (size_t)(rb + rowB) * EE + 8*t + 2*tig] =
                make_float2(1.f/(1.f+__expf(-zB0)), 1.f/(1.f+__expf(-zB1)));
        }
    }

    // prefetch K[0]
    {
        const uint4* Kh = (const uint4*)g_Khi;
        const uint4* Kl = (const uint4*)g_Klo;
        #pragma unroll
        for (int i = 0; i < 4; i++) {
            int u = i * NT + tid;
            int row = u >> 5, c = u & 31;
            uint32_t o = (uint32_t)(row * 512 + ((c ^ (row & 7)) << 4));
            cpasync16(sb + S_B0 + o, Kh + u);
            cpasync16(sb + S_B1 + o, Kl + u);
        }
        CP_COMMIT();
    }

    for (int e = 0; e < EE; e++) {
        CP_WAIT0();
        __syncthreads();        // (1) K resident

        // ======== GEMM1: logits[16 rows x 64 cols per warp], 3-term ========
        float acc[8][4] = {};
        {
            uint32_t al[4], bh[4], bl[4];
            #pragma unroll 2
            for (int ks = 0; ks < 16; ks++) {
                ldsm4(al, addrA(sb + S_XLO, 16 * warp, 2 * ks, 512, lane));
                const uint32_t* ah = xh + 4 * ks;
                #pragma unroll
                for (int p = 0; p < 4; p++) {
                    ldsm4(bh, addrB(sb + S_B0, 16 * p, 2 * ks, 512, lane));
                    ldsm4(bl, addrB(sb + S_B1, 16 * p, 2 * ks, 512, lane));
                    mma_bf16(acc[2*p],   ah, bh); mma_bf16(acc[2*p+1], ah, bh + 2);
                    mma_bf16(acc[2*p],   al, bh); mma_bf16(acc[2*p+1], al, bh + 2);
                    mma_bf16(acc[2*p],   ah, bl); mma_bf16(acc[2*p+1], ah, bl + 2);
                }
            }
        }
        __syncthreads();        // (2) K reads done -> V load can start

        // issue V load (overlaps softmax epilogue)
        {
            const uint4* Vh = (const uint4*)g_Vthi + e * 2048;
            const uint4* Vl = (const uint4*)g_Vtlo + e * 2048;
            #pragma unroll
            for (int i = 0; i < 4; i++) {
                int u = i * NT + tid;
                int row = u >> 3, c = u & 7;
                uint32_t o = (uint32_t)(row * 128 + ((c ^ (row & 7)) << 4));
                cpasync16(sb + S_B0 + o, Vh + u);
                cpasync16(sb + S_B1 + o, Vl + u);
            }
            CP_COMMIT();
        }

        // ======== softmax (full row in-warp; logits ~N(0,1/16): no max-sub) ========
        uint32_t aH[16], aL[16];
        {
            float sA = 0.f, sB = 0.f;
            #pragma unroll
            for (int t = 0; t < 8; t++) {
                acc[t][0] = __expf(acc[t][0] * 0.0625f); sA += acc[t][0];
                acc[t][1] = __expf(acc[t][1] * 0.0625f); sA += acc[t][1];
                acc[t][2] = __expf(acc[t][2] * 0.0625f); sB += acc[t][2];
                acc[t][3] = __expf(acc[t][3] * 0.0625f); sB += acc[t][3];
            }
            sA += __shfl_xor_sync(0xffffffffu, sA, 1);
            sA += __shfl_xor_sync(0xffffffffu, sA, 2);
            sB += __shfl_xor_sync(0xffffffffu, sB, 1);
            sB += __shfl_xor_sync(0xffffffffu, sB, 2);
            float iA = 1.f / sA, iB = 1.f / sB;
            float* oaA = &out[O_A + ((size_t)(rb + rowA) * EE + e) * MM];
            float* oaB = &out[O_A + ((size_t)(rb + rowB) * EE + e) * MM];
            #pragma unroll
            for (int t = 0; t < 8; t++) {
                float a0 = acc[t][0] * iA, a1 = acc[t][1] * iA;
                float b0 = acc[t][2] * iB, b1 = acc[t][3] * iB;
                *(float2*)&oaA[8*t + 2*tig] = make_float2(a0, a1);
                *(float2*)&oaB[8*t + 2*tig] = make_float2(b0, b1);
                acc[t][0] = a0; acc[t][1] = a1; acc[t][2] = b0; acc[t][3] = b1;
            }
            // C-frag -> A-frag (attn stays in registers; no smem, no ldsm)
            #pragma unroll
            for (int ks = 0; ks < 4; ks++) {
                aH[4*ks+0] = packhi2(acc[2*ks][0],   acc[2*ks][1]);
                aH[4*ks+1] = packhi2(acc[2*ks][2],   acc[2*ks][3]);
                aH[4*ks+2] = packhi2(acc[2*ks+1][0], acc[2*ks+1][1]);
                aH[4*ks+3] = packhi2(acc[2*ks+1][2], acc[2*ks+1][3]);
                aL[4*ks+0] = packlo2(acc[2*ks][0],   acc[2*ks][1]);
                aL[4*ks+1] = packlo2(acc[2*ks][2],   acc[2*ks][3]);
                aL[4*ks+2] = packlo2(acc[2*ks+1][0], acc[2*ks+1][1]);
                aL[4*ks+3] = packlo2(acc[2*ks+1][2], acc[2*ks+1][3]);
            }
        }
        CP_WAIT0();
        __syncthreads();        // (3) V resident

        // ======== GEMM2: y[16 rows x 256 cols] in 16-col chunks, 3-term ========
        float pxA = 0.f, pnA = 0.f, pxB = 0.f, pnB = 0.f;
        const float* xgA = &x[(size_t)(rb + rowA) * DD];
        const float* xgB = &x[(size_t)(rb + rowB) * DD];
        float* oyA = &out[O_Y + ((size_t)(rb + rowA) * EE + e) * DD];
        float* oyB = &out[O_Y + ((size_t)(rb + rowB) * EE + e) * DD];
        #pragma unroll 2
        for (int ch = 0; ch < 16; ch++) {
            float acc2[2][4] = {};
            {
                uint32_t bh[4], bl[4];
                #pragma unroll
                for (int ks = 0; ks < 4; ks++) {
                    ldsm4(bh, addrB(sb + S_B0, 16 * ch, 2 * ks, 128, lane));
                    ldsm4(bl, addrB(sb + S_B1, 16 * ch, 2 * ks, 128, lane));
                    const uint32_t* ah = aH + 4 * ks;
                    const uint32_t* al = aL + 4 * ks;
                    mma_bf16(acc2[0], ah, bh); mma_bf16(acc2[1], ah, bh + 2);
                    mma_bf16(acc2[0], al, bh); mma_bf16(acc2[1], al, bh + 2);
                    mma_bf16(acc2[0], ah, bl); mma_bf16(acc2[1], ah, bl + 2);
                }
            }
            #pragma unroll
            for (int j = 0; j < 2; j++) {
                int d = 16 * ch + 8 * j + 2 * tig;
                float y0 = acc2[j][0], y1 = acc2[j][1];
                float z0 = acc2[j][2], z1 = acc2[j][3];
                *(float2*)&oyA[d] = make_float2(y0, y1);
                *(float2*)&oyB[d] = make_float2(z0, z1);
                float2 xa = *(const float2*)&xgA[d];
                float2 xb = *(const float2*)&xgB[d];
                pxA = fmaf(xa.x, y0, fmaf(xa.y, y1, pxA));
                pnA = fmaf(y0, y0, fmaf(y1, y1, pnA));
                pxB = fmaf(xb.x, z0, fmaf(xb.y, z1, pxB));
                pnB = fmaf(z0, z0, fmaf(z1, z1, pnB));
            }
        }

        pxA += __shfl_xor_sync(0xffffffffu, pxA, 1);
        pxA += __shfl_xor_sync(0xffffffffu, pxA, 2);
        pnA += __shfl_xor_sync(0xffffffffu, pnA, 1);
        pnA += __shfl_xor_sync(0xffffffffu, pnA, 2);
        pxB += __shfl_xor_sync(0xffffffffu, pxB, 1);
        pxB += __shfl_xor_sync(0xffffffffu, pxB, 2);
        pnB += __shfl_xor_sync(0xffffffffu, pnB, 1);
        pnB += __shfl_xor_sync(0xffffffffu, pnB, 2);
        if (tig == 0) {
            g_px[(size_t)(rb + rowA) * EE + e] = pxA;
            g_pn[(size_t)(rb + rowA) * EE + e] = pnA;
            g_px[(size_t)(rb + rowB) * EE + e] = pxB;
            g_pn[(size_t)(rb + rowB) * EE + e] = pnB;
        }
        __syncthreads();        // (4) V reads done -> next K load can start

        if (e + 1 < EE) {
            const uint4* Kh = (const uint4*)g_Khi + (e + 1) * 2048;
            const uint4* Kl = (const uint4*)g_Klo + (e + 1) * 2048;
            #pragma unroll
            for (int i = 0; i < 4; i++) {
                int u = i * NT + tid;
                int row = u >> 5, c = u & 31;
                uint32_t o = (uint32_t)(row * 512 + ((c ^ (row & 7)) << 4));
                cpasync16(sb + S_B0 + o, Kh + u);
                cpasync16(sb + S_B1 + o, Kl + u);
            }
            CP_COMMIT();
        }
    }
}

// ================= finisher: familiarity + argmax =================
__global__ __launch_bounds__(256) void more_fin(float* __restrict__ out) {
    int r = blockIdx.x * 256 + threadIdx.x;
    if (r >= BB) return;
    float xn = g_xn[r];
    float bestf = -INFINITY;
    int beste = 0;
    const float* gp = &out[O_G + (size_t)r * EE];
    #pragma unroll
    for (int e = 0; e < EE; e++) {
        float px = g_px[(size_t)r * EE + e];
        float pn = g_pn[(size_t)r * EE + e];
        float cosv = px / (xn * sqrtf(pn) + 1e-8f);
        float f = gp[e] * cosv;
        if (f > bestf) { bestf = f; beste = e; }
    }
    out[O_W + r] = (float)beste;
    out[O_S + r] = bestf;
}

extern "C" void kernel_launch(void* const* d_in, const int* in_sizes, int n_in,
                              void* d_out, int out_size) {
    (void)in_sizes; (void)n_in; (void)out_size;
    const float* x  = (const float*)d_in[0];
    const float* K  = (const float*)d_in[1];
    const float* V  = (const float*)d_in[2];
    const float* wg = (const float*)d_in[3];
    const float* bg = (const float*)d_in[4];
    float* out = (float*)d_out;

    pp_kernel<<<256, 256>>>(K, V, wg);

    cudaFuncSetAttribute(more_mma, cudaFuncAttributeMaxDynamicSharedMemorySize, SMEM_REQ);
    more_mma<<<BB / RT, NT, SMEM_REQ>>>(x, bg, out);

    more_fin<<<BB / 256, 256>>>(out);
}

// round 10
// speedup vs baseline: 1.0244x; 1.0244x over previous
#include <cuda_runtime.h>
#include <cuda_bf16.h>
#include <cstdint>
#include <math.h>

#define BB 32768
#define EE 16
#define MM 64
#define DD 256
#define RT 128
#define NT 256

#define O_W ((size_t)0)
#define O_S ((size_t)BB)
#define O_Y ((size_t)(2*BB))
#define O_G (O_Y + (size_t)BB*EE*DD)
#define O_A (O_G + (size_t)BB*EE)

// preconverted operands + scratch
__device__ __nv_bfloat16 g_Khi[EE*MM*DD];
__device__ __nv_bfloat16 g_Klo[EE*MM*DD];
__device__ __nv_bfloat16 g_Vthi[EE*DD*MM];   // [E][D][M]
__device__ __nv_bfloat16 g_Vtlo[EE*DD*MM];
__device__ __nv_bfloat16 g_wghi[EE*DD];
__device__ __nv_bfloat16 g_wglo[EE*DD];
__device__ float g_px[(size_t)BB*EE];
__device__ float g_pn[(size_t)BB*EE];
__device__ float g_xn[BB];

// smem map
#define S_XLO 0        // 65536: x_lo [128 rows][512B] swizzled
#define S_KB0 65536    // 32768: K_hi
#define S_KB1 98304    // 32768: K_lo
#define S_VB0 131072   // 32768: Vt_hi (wg_hi in prologue)
#define S_VB1 163840   // 32768: Vt_lo (wg_lo)
#define SMEM_REQ 196608

__device__ __forceinline__ uint32_t smem_u32(const void* p) {
    uint32_t a;
    asm("{ .reg .u64 t; cvta.to.shared.u64 t, %1; cvt.u32.u64 %0, t; }" : "=r"(a) : "l"(p));
    return a;
}
__device__ __forceinline__ void ldsm4(uint32_t* r, uint32_t addr) {
    asm volatile("ldmatrix.sync.aligned.m8n8.x4.shared.b16 {%0,%1,%2,%3}, [%4];"
        : "=r"(r[0]), "=r"(r[1]), "=r"(r[2]), "=r"(r[3]) : "r"(addr));
}
__device__ __forceinline__ void mma_bf16(float* c, const uint32_t* a, const uint32_t* b) {
    asm volatile("mma.sync.aligned.m16n8k16.row.col.f32.bf16.bf16.f32 "
        "{%0,%1,%2,%3}, {%4,%5,%6,%7}, {%8,%9}, {%0,%1,%2,%3};"
        : "+f"(c[0]), "+f"(c[1]), "+f"(c[2]), "+f"(c[3])
        : "r"(a[0]), "r"(a[1]), "r"(a[2]), "r"(a[3]), "r"(b[0]), "r"(b[1]));
}
__device__ __forceinline__ void cpasync16(uint32_t dst, const void* src) {
    asm volatile("cp.async.cg.shared.global [%0], [%1], 16;" :: "r"(dst), "l"(src));
}
#define CP_COMMIT() asm volatile("cp.async.commit_group;" ::: "memory")
#define CP_WAIT0()  asm volatile("cp.async.wait_group 0;" ::: "memory")

__device__ __forceinline__ uint32_t addrA(uint32_t base, int r0, int c0, int rb, int lane) {
    int row = r0 + (lane & 15);
    int c = c0 + (lane >> 4);
    return base + row * rb + ((c ^ (row & 7)) << 4);
}
__device__ __forceinline__ uint32_t addrB(uint32_t base, int n0, int c0, int rb, int lane) {
    int row = n0 + ((lane >> 4) << 3) + (lane & 7);
    int c = c0 + ((lane >> 3) & 1);
    return base + row * rb + ((c ^ (row & 7)) << 4);
}
__device__ __forceinline__ uint32_t pack2(__nv_bfloat16 a, __nv_bfloat16 b) {
    return ((uint32_t)__bfloat16_as_ushort(b) << 16) | (uint32_t)__bfloat16_as_ushort(a);
}
__device__ __forceinline__ void split_bf(float v, __nv_bfloat16& h, __nv_bfloat16& l) {
    h = __float2bfloat16(v);
    l = __float2bfloat16(v - __bfloat162float(h));
}
__device__ __forceinline__ uint32_t packhi2(float a, float b) {
    return pack2(__float2bfloat16(a), __float2bfloat16(b));
}
__device__ __forceinline__ uint32_t packlo2(float a, float b) {
    __nv_bfloat16 ha = __float2bfloat16(a), hb = __float2bfloat16(b);
    return pack2(__float2bfloat16(a - __bfloat162float(ha)),
                 __float2bfloat16(b - __bfloat162float(hb)));
}

// ---------------- preprocess ----------------
__global__ void pp_kernel(const float* __restrict__ K, const float* __restrict__ V,
                          const float* __restrict__ wg) {
    const int total = EE * MM * DD;
    for (int idx = blockIdx.x * blockDim.x + threadIdx.x; idx < total;
         idx += gridDim.x * blockDim.x) {
        __nv_bfloat16 h, l;
        split_bf(K[idx], h, l);
        g_Khi[idx] = h; g_Klo[idx] = l;
        int e = idx >> 14, rem = idx & 16383, d = rem >> 6, m = rem & 63;
        split_bf(V[(e << 14) + m * DD + d], h, l);
        g_Vthi[idx] = h; g_Vtlo[idx] = l;
        if (idx < EE * DD) { split_bf(wg[idx], h, l); g_wghi[idx] = h; g_wglo[idx] = l; }
    }
}

// ================= main fused kernel =================
__global__ __launch_bounds__(NT, 1) void more_mma(
    const float* __restrict__ x, const float* __restrict__ bg,
    float* __restrict__ out)
{
    extern __shared__ char smem[];
    const uint32_t sb = smem_u32(smem);

    const int tid  = threadIdx.x;
    const int warp = tid >> 5;
    const int lane = tid & 31;
    const int gid  = lane >> 2;
    const int tig  = lane & 3;
    const int rb   = blockIdx.x * RT;
    const int rowA = 16 * warp + gid;      // 0..127
    const int rowB = rowA + 8;

    // ---- prologue: x_lo -> smem tile; x_hi -> persistent A-frag registers ----
    #pragma unroll 4
    for (int i = 0; i < 32; i++) {
        int f4i = i * NT + tid;
        int r = f4i >> 6, c4 = f4i & 63;
        float4 v = *(const float4*)&x[(size_t)(rb + r) * DD + c4 * 4];
        __nv_bfloat16 h0,h1,h2,h3,l0,l1,l2,l3;
        split_bf(v.x,h0,l0); split_bf(v.y,h1,l1); split_bf(v.z,h2,l2); split_bf(v.w,h3,l3);
        int o = r * 512 + ((((c4 >> 1) ^ (r & 7))) << 4) + (c4 & 1) * 8;
        *(uint2*)(smem + S_XLO + o) = make_uint2(pack2(l0,l1), pack2(l2,l3));
    }
    uint32_t xh[64];   // 16 k-chunks x 4 regs; ALL uses fully unrolled (const indices)
    {
        const float* xpA = &x[(size_t)(rb + rowA) * DD + 2 * tig];
        const float* xpB = &x[(size_t)(rb + rowB) * DD + 2 * tig];
        #pragma unroll
        for (int ks = 0; ks < 16; ks++) {
            float2 g0 = *(const float2*)&xpA[16 * ks];
            float2 g1 = *(const float2*)&xpB[16 * ks];
            float2 g2 = *(const float2*)&xpA[16 * ks + 8];
            float2 g3 = *(const float2*)&xpB[16 * ks + 8];
            xh[4*ks+0] = packhi2(g0.x, g0.y);
            xh[4*ks+1] = packhi2(g1.x, g1.y);
            xh[4*ks+2] = packhi2(g2.x, g2.y);
            xh[4*ks+3] = packhi2(g3.x, g3.y);
        }
    }
    // wg hi -> VB0, lo -> VB1 (16 rows x 512B = 512 uint4)
    {
        const uint4* Wh = (const uint4*)g_wghi;
        const uint4* Wl = (const uint4*)g_wglo;
        #pragma unroll
        for (int i = 0; i < 2; i++) {
            int u = i * NT + tid;
            int row = u >> 5, c = u & 31;
            int o = row * 512 + ((c ^ (row & 7)) << 4);
            *(uint4*)(smem + S_VB0 + o) = Wh[u];
            *(uint4*)(smem + S_VB1 + o) = Wl[u];
        }
    }
    // x row norms
    {
        const float4* xr = (const float4*)&x[(size_t)(rb + (tid & 127)) * DD];
        if (tid < RT) {
            float s = 0.f;
            #pragma unroll 8
            for (int j = 0; j < 64; j++) {
                float4 v = xr[j];
                s = fmaf(v.x, v.x, fmaf(v.y, v.y, fmaf(v.z, v.z, fmaf(v.w, v.w, s))));
            }
            g_xn[rb + tid] = sqrtf(s);
        }
    }
    __syncthreads();

    // prefetch K[0] (KB is untouched so far)
    {
        const uint4* Kh = (const uint4*)g_Khi;
        const uint4* Kl = (const uint4*)g_Klo;
        #pragma unroll
        for (int i = 0; i < 8; i++) {
            int u = i * NT + tid;
            int row = u >> 5, c = u & 31;
            uint32_t o = (uint32_t)(row * 512 + ((c ^ (row & 7)) << 4));
            cpasync16(sb + S_KB0 + o, Kh + u);
            cpasync16(sb + S_KB1 + o, Kl + u);
        }
        CP_COMMIT();
    }

    // ---- gate GEMM: full N=16 per warp, 3-term (FULL unroll: xh const-indexed) ----
    {
        float accg[2][4] = {};
        uint32_t al[4], bh[4], bl[4];
        #pragma unroll
        for (int ks = 0; ks < 16; ks++) {
            ldsm4(al, addrA(sb + S_XLO, 16 * warp, 2 * ks, 512, lane));
            ldsm4(bh, addrB(sb + S_VB0, 0, 2 * ks, 512, lane));
            ldsm4(bl, addrB(sb + S_VB1, 0, 2 * ks, 512, lane));
            const uint32_t* ah = xh + 4 * ks;
            mma_bf16(accg[0], ah, bh); mma_bf16(accg[1], ah, bh + 2);
            mma_bf16(accg[0], al, bh); mma_bf16(accg[1], al, bh + 2);
            mma_bf16(accg[0], ah, bl); mma_bf16(accg[1], ah, bl + 2);
        }
        #pragma unroll
        for (int t = 0; t < 2; t++) {
            float zA0 = accg[t][0] + bg[8*t + 2*tig];
            float zA1 = accg[t][1] + bg[8*t + 2*tig + 1];
            float zB0 = accg[t][2] + bg[8*t + 2*tig];
            float zB1 = accg[t][3] + bg[8*t + 2*tig + 1];
            *(float2*)&out[O_G + (size_t)(rb + rowA) * EE + 8*t + 2*tig] =
                make_float2(1.f/(1.f+__expf(-zA0)), 1.f/(1.f+__expf(-zA1)));
            *(float2*)&out[O_G + (size_t)(rb + rowB) * EE + 8*t + 2*tig] =
                make_float2(1.f/(1.f+__expf(-zB0)), 1.f/(1.f+__expf(-zB1)));
        }
    }
    __syncthreads();   // gate reads of VB done -> V[0] prefetch may overwrite

    // prefetch V[0]
    {
        const uint4* Vh = (const uint4*)g_Vthi;
        const uint4* Vl = (const uint4*)g_Vtlo;
        #pragma unroll
        for (int i = 0; i < 8; i++) {
            int u = i * NT + tid;
            int row = u >> 3, c = u & 7;
            uint32_t o = (uint32_t)(row * 128 + ((c ^ (row & 7)) << 4));
            cpasync16(sb + S_VB0 + o, Vh + u);
            cpasync16(sb + S_VB1 + o, Vl + u);
        }
        CP_COMMIT();
    }

    for (int e = 0; e < EE; e++) {
        CP_WAIT0();
        __syncthreads();        // (1) K(e) + V(e) resident

        // ======== GEMM1: logits[16 rows x 64 cols per warp], 3-term, FULL unroll ========
        float acc[8][4] = {};
        {
            uint32_t al[4], bh[4], bl[4];
            #pragma unroll
            for (int ks = 0; ks < 16; ks++) {
                ldsm4(al, addrA(sb + S_XLO, 16 * warp, 2 * ks, 512, lane));
                const uint32_t* ah = xh + 4 * ks;
                #pragma unroll
                for (int p = 0; p < 4; p++) {
                    ldsm4(bh, addrB(sb + S_KB0, 16 * p, 2 * ks, 512, lane));
                    ldsm4(bl, addrB(sb + S_KB1, 16 * p, 2 * ks, 512, lane));
                    mma_bf16(acc[2*p],   ah, bh); mma_bf16(acc[2*p+1], ah, bh + 2);
                    mma_bf16(acc[2*p],   al, bh); mma_bf16(acc[2*p+1], al, bh + 2);
                    mma_bf16(acc[2*p],   ah, bl); mma_bf16(acc[2*p+1], ah, bl + 2);
                }
            }
        }
        __syncthreads();        // (2) K reads done -> K(e+1) prefetch safe

        if (e + 1 < EE) {
            const uint4* Kh = (const uint4*)g_Khi + (e + 1) * 2048;
            const uint4* Kl = (const uint4*)g_Klo + (e + 1) * 2048;
            #pragma unroll
            for (int i = 0; i < 8; i++) {
                int u = i * NT + tid;
                int row = u >> 5, c = u & 31;
                uint32_t o = (uint32_t)(row * 512 + ((c ^ (row & 7)) << 4));
                cpasync16(sb + S_KB0 + o, Kh + u);
                cpasync16(sb + S_KB1 + o, Kl + u);
            }
            CP_COMMIT();
        }

        // ======== softmax (full row in-warp; logits ~N(0,1/16): no max-sub) ========
        uint32_t aH[16], aL[16];
        {
            float sA = 0.f, sB = 0.f;
            #pragma unroll
            for (int t = 0; t < 8; t++) {
                acc[t][0] = __expf(acc[t][0] * 0.0625f); sA += acc[t][0];
                acc[t][1] = __expf(acc[t][1] * 0.0625f); sA += acc[t][1];
                acc[t][2] = __expf(acc[t][2] * 0.0625f); sB += acc[t][2];
                acc[t][3] = __expf(acc[t][3] * 0.0625f); sB += acc[t][3];
            }
            sA += __shfl_xor_sync(0xffffffffu, sA, 1);
            sA += __shfl_xor_sync(0xffffffffu, sA, 2);
            sB += __shfl_xor_sync(0xffffffffu, sB, 1);
            sB += __shfl_xor_sync(0xffffffffu, sB, 2);
            float iA = 1.f / sA, iB = 1.f / sB;
            float* oaA = &out[O_A + ((size_t)(rb + rowA) * EE + e) * MM];
            float* oaB = &out[O_A + ((size_t)(rb + rowB) * EE + e) * MM];
            #pragma unroll
            for (int t = 0; t < 8; t++) {
                float a0 = acc[t][0] * iA, a1 = acc[t][1] * iA;
                float b0 = acc[t][2] * iB, b1 = acc[t][3] * iB;
                *(float2*)&oaA[8*t + 2*tig] = make_float2(a0, a1);
                *(float2*)&oaB[8*t + 2*tig] = make_float2(b0, b1);
                acc[t][0] = a0; acc[t][1] = a1; acc[t][2] = b0; acc[t][3] = b1;
            }
            // C-frag -> A-frag in registers (attn never touches smem)
            #pragma unroll
            for (int ks = 0; ks < 4; ks++) {
                aH[4*ks+0] = packhi2(acc[2*ks][0],   acc[2*ks][1]);
                aH[4*ks+1] = packhi2(acc[2*ks][2],   acc[2*ks][3]);
                aH[4*ks+2] = packhi2(acc[2*ks+1][0], acc[2*ks+1][1]);
                aH[4*ks+3] = packhi2(acc[2*ks+1][2], acc[2*ks+1][3]);
                aL[4*ks+0] = packlo2(acc[2*ks][0],   acc[2*ks][1]);
                aL[4*ks+1] = packlo2(acc[2*ks][2],   acc[2*ks][3]);
                aL[4*ks+2] = packlo2(acc[2*ks+1][0], acc[2*ks+1][1]);
                aL[4*ks+3] = packlo2(acc[2*ks+1][2], acc[2*ks+1][3]);
            }
        }

        // ======== GEMM2: y[16 rows x 256 cols] in 16-col chunks, 3-term ========
        float pxA = 0.f, pnA = 0.f, pxB = 0.f, pnB = 0.f;
        const float* xgA = &x[(size_t)(rb + rowA) * DD];
        const float* xgB = &x[(size_t)(rb + rowB) * DD];
        float* oyA = &out[O_Y + ((size_t)(rb + rowA) * EE + e) * DD];
        float* oyB = &out[O_Y + ((size_t)(rb + rowB) * EE + e) * DD];
        #pragma unroll 2
        for (int ch = 0; ch < 16; ch++) {
            float acc2[2][4] = {};
            {
                uint32_t bh[4], bl[4];
                #pragma unroll
                for (int ks = 0; ks < 4; ks++) {
                    ldsm4(bh, addrB(sb + S_VB0, 16 * ch, 2 * ks, 128, lane));
                    ldsm4(bl, addrB(sb + S_VB1, 16 * ch, 2 * ks, 128, lane));
                    const uint32_t* ah = aH + 4 * ks;
                    const uint32_t* al = aL + 4 * ks;
                    mma_bf16(acc2[0], ah, bh); mma_bf16(acc2[1], ah, bh + 2);
                    mma_bf16(acc2[0], al, bh); mma_bf16(acc2[1], al, bh + 2);
                    mma_bf16(acc2[0], ah, bl); mma_bf16(acc2[1], ah, bl + 2);
                }
            }
            #pragma unroll
            for (int j = 0; j < 2; j++) {
                int d = 16 * ch + 8 * j + 2 * tig;
                float y0 = acc2[j][0], y1 = acc2[j][1];
                float z0 = acc2[j][2], z1 = acc2[j][3];
                *(float2*)&oyA[d] = make_float2(y0, y1);
                *(float2*)&oyB[d] = make_float2(z0, z1);
                float2 xa = *(const float2*)&xgA[d];
                float2 xb = *(const float2*)&xgB[d];
                pxA = fmaf(xa.x, y0, fmaf(xa.y, y1, pxA));
                pnA = fmaf(y0, y0, fmaf(y1, y1, pnA));
                pxB = fmaf(xb.x, z0, fmaf(xb.y, z1, pxB));
                pnB = fmaf(z0, z0, fmaf(z1, z1, pnB));
            }
        }
        __syncthreads();        // (3) V reads done -> V(e+1) prefetch safe

        if (e + 1 < EE) {
            const uint4* Vh = (const uint4*)g_Vthi + (e + 1) * 2048;
            const uint4* Vl = (const uint4*)g_Vtlo + (e + 1) * 2048;
            #pragma unroll
            for (int i = 0; i < 8; i++) {
                int u = i * NT + tid;
                int row = u >> 3, c = u & 7;
                uint32_t o = (uint32_t)(row * 128 + ((c ^ (row & 7)) << 4));
                cpasync16(sb + S_VB0 + o, Vh + u);
                cpasync16(sb + S_VB1 + o, Vl + u);
            }
            CP_COMMIT();
        }

        // px/pn reduce + store (overlaps V prefetch)
        pxA += __shfl_xor_sync(0xffffffffu, pxA, 1);
        pxA += __shfl_xor_sync(0xffffffffu, pxA, 2);
        pnA += __shfl_xor_sync(0xffffffffu, pnA, 1);
        pnA += __shfl_xor_sync(0xffffffffu, pnA, 2);
        pxB += __shfl_xor_sync(0xffffffffu, pxB, 1);
        pxB += __shfl_xor_sync(0xffffffffu, pxB, 2);
        pnB += __shfl_xor_sync(0xffffffffu, pnB, 1);
        pnB += __shfl_xor_sync(0xffffffffu, pnB, 2);
        if (tig == 0) {
            g_px[(size_t)(rb + rowA) * EE + e] = pxA;
            g_pn[(size_t)(rb + rowA) * EE + e] = pnA;
            g_px[(size_t)(rb + rowB) * EE + e] = pxB;
            g_pn[(size_t)(rb + rowB) * EE + e] = pnB;
        }
    }
}

// ================= finisher: familiarity + argmax =================
__global__ __launch_bounds__(256) void more_fin(float* __restrict__ out) {
    int r = blockIdx.x * 256 + threadIdx.x;
    if (r >= BB) return;
    float xn = g_xn[r];
    float bestf = -INFINITY;
    int beste = 0;
    const float* gp = &out[O_G + (size_t)r * EE];
    #pragma unroll
    for (int e = 0; e < EE; e++) {
        float px = g_px[(size_t)r * EE + e];
        float pn = g_pn[(size_t)r * EE + e];
        float cosv = px / (xn * sqrtf(pn) + 1e-8f);
        float f = gp[e] * cosv;
        if (f > bestf) { bestf = f; beste = e; }
    }
    out[O_W + r] = (float)beste;
    out[O_S + r] = bestf;
}

extern "C" void kernel_launch(void* const* d_in, const int* in_sizes, int n_in,
                              void* d_out, int out_size) {
    (void)in_sizes; (void)n_in; (void)out_size;
    const float* x  = (const float*)d_in[0];
    const float* K  = (const float*)d_in[1];
    const float* V  = (const float*)d_in[2];
    const float* wg = (const float*)d_in[3];
    const float* bg = (const float*)d_in[4];
    float* out = (float*)d_out;

    pp_kernel<<<256, 256>>>(K, V, wg);

    cudaFuncSetAttribute(more_mma, cudaFuncAttributeMaxDynamicSharedMemorySize, SMEM_REQ);
    more_mma<<<BB / RT, NT, SMEM_REQ>>>(x, bg, out);

    more_fin<<<BB / 256, 256>>>(out);
}

// round 11
// speedup vs baseline: 1.1698x; 1.1419x over previous
#include <cuda_runtime.h>
#include <cuda_bf16.h>
#include <cstdint>
#include <math.h>

#define BB 32768
#define EE 16
#define MM 64
#define DD 256
#define RT 64
#define NT 128

#define O_W ((size_t)0)
#define O_S ((size_t)BB)
#define O_Y ((size_t)(2*BB))
#define O_G (O_Y + (size_t)BB*EE*DD)
#define O_A (O_G + (size_t)BB*EE)

// preconverted operands + scratch
__device__ __nv_bfloat16 g_Khi[EE*MM*DD];
__device__ __nv_bfloat16 g_Klo[EE*MM*DD];
__device__ __nv_bfloat16 g_Vthi[EE*DD*MM];   // [E][D][M]
__device__ __nv_bfloat16 g_Vtlo[EE*DD*MM];
__device__ __nv_bfloat16 g_wghi[EE*DD];
__device__ __nv_bfloat16 g_wglo[EE*DD];
__device__ float g_px[(size_t)BB*EE];
__device__ float g_pn[(size_t)BB*EE];
__device__ float g_xn[BB];

// smem: ONE shared hi/lo buffer pair (wg -> K(e) -> V(e) -> K(e+1) ...)
#define S_B0 0        // 32768
#define S_B1 32768    // 32768
#define SMEM_REQ 65536

__device__ __forceinline__ uint32_t smem_u32(const void* p) {
    uint32_t a;
    asm("{ .reg .u64 t; cvta.to.shared.u64 t, %1; cvt.u32.u64 %0, t; }" : "=r"(a) : "l"(p));
    return a;
}
__device__ __forceinline__ void ldsm4(uint32_t* r, uint32_t addr) {
    asm volatile("ldmatrix.sync.aligned.m8n8.x4.shared.b16 {%0,%1,%2,%3}, [%4];"
        : "=r"(r[0]), "=r"(r[1]), "=r"(r[2]), "=r"(r[3]) : "r"(addr));
}
__device__ __forceinline__ void mma_bf16(float* c, const uint32_t* a, const uint32_t* b) {
    asm volatile("mma.sync.aligned.m16n8k16.row.col.f32.bf16.bf16.f32 "
        "{%0,%1,%2,%3}, {%4,%5,%6,%7}, {%8,%9}, {%0,%1,%2,%3};"
        : "+f"(c[0]), "+f"(c[1]), "+f"(c[2]), "+f"(c[3])
        : "r"(a[0]), "r"(a[1]), "r"(a[2]), "r"(a[3]), "r"(b[0]), "r"(b[1]));
}
__device__ __forceinline__ void cpasync16(uint32_t dst, const void* src) {
    asm volatile("cp.async.cg.shared.global [%0], [%1], 16;" :: "r"(dst), "l"(src));
}
#define CP_COMMIT() asm volatile("cp.async.commit_group;" ::: "memory")
#define CP_WAIT0()  asm volatile("cp.async.wait_group 0;" ::: "memory")

__device__ __forceinline__ uint32_t addrB(uint32_t base, int n0, int c0, int rb, int lane) {
    int row = n0 + ((lane >> 4) << 3) + (lane & 7);
    int c = c0 + ((lane >> 3) & 1);
    return base + row * rb + ((c ^ (row & 7)) << 4);
}
__device__ __forceinline__ uint32_t pack2(__nv_bfloat16 a, __nv_bfloat16 b) {
    return ((uint32_t)__bfloat16_as_ushort(b) << 16) | (uint32_t)__bfloat16_as_ushort(a);
}
__device__ __forceinline__ void split_bf(float v, __nv_bfloat16& h, __nv_bfloat16& l) {
    h = __float2bfloat16(v);
    l = __float2bfloat16(v - __bfloat162float(h));
}
__device__ __forceinline__ uint32_t packhi2(float a, float b) {
    return pack2(__float2bfloat16(a), __float2bfloat16(b));
}
__device__ __forceinline__ uint32_t packlo2(float a, float b) {
    __nv_bfloat16 ha = __float2bfloat16(a), hb = __float2bfloat16(b);
    return pack2(__float2bfloat16(a - __bfloat162float(ha)),
                 __float2bfloat16(b - __bfloat162float(hb)));
}
__device__ __forceinline__ float b2f_lo(uint32_t u) { return __uint_as_float(u << 16); }
__device__ __forceinline__ float b2f_hi(uint32_t u) { return __uint_as_float(u & 0xFFFF0000u); }

// ---------------- preprocess ----------------
__global__ void pp_kernel(const float* __restrict__ K, const float* __restrict__ V,
                          const float* __restrict__ wg) {
    const int total = EE * MM * DD;
    for (int idx = blockIdx.x * blockDim.x + threadIdx.x; idx < total;
         idx += gridDim.x * blockDim.x) {
        __nv_bfloat16 h, l;
        split_bf(K[idx], h, l);
        g_Khi[idx] = h; g_Klo[idx] = l;
        int e = idx >> 14, rem = idx & 16383, d = rem >> 6, m = rem & 63;
        split_bf(V[(e << 14) + m * DD + d], h, l);
        g_Vthi[idx] = h; g_Vtlo[idx] = l;
        if (idx < EE * DD) { split_bf(wg[idx], h, l); g_wghi[idx] = h; g_wglo[idx] = l; }
    }
}

// ================= main fused kernel: 2 CTAs/SM, all-register A operands =================
__global__ __launch_bounds__(NT, 2) void more_mma(
    const float* __restrict__ x, const float* __restrict__ bg,
    float* __restrict__ out)
{
    extern __shared__ char smem[];
    const uint32_t sb = smem_u32(smem);

    const int tid  = threadIdx.x;
    const int warp = tid >> 5;              // 0..3
    const int lane = tid & 31;
    const int gid  = lane >> 2;
    const int tig  = lane & 3;
    const int rb   = blockIdx.x * RT;
    const int rowA = 16 * warp + gid;       // 0..63
    const int rowB = rowA + 8;

    // ---- x hi/lo -> persistent A-fragment registers (fully unrolled) ----
    uint32_t xh[64], xl[64];
    {
        const float* xpA = &x[(size_t)(rb + rowA) * DD + 2 * tig];
        const float* xpB = &x[(size_t)(rb + rowB) * DD + 2 * tig];
        #pragma unroll
        for (int ks = 0; ks < 16; ks++) {
            float2 g0 = *(const float2*)&xpA[16 * ks];
            float2 g1 = *(const float2*)&xpB[16 * ks];
            float2 g2 = *(const float2*)&xpA[16 * ks + 8];
            float2 g3 = *(const float2*)&xpB[16 * ks + 8];
            xh[4*ks+0] = packhi2(g0.x, g0.y);  xl[4*ks+0] = packlo2(g0.x, g0.y);
            xh[4*ks+1] = packhi2(g1.x, g1.y);  xl[4*ks+1] = packlo2(g1.x, g1.y);
            xh[4*ks+2] = packhi2(g2.x, g2.y);  xl[4*ks+2] = packlo2(g2.x, g2.y);
            xh[4*ks+3] = packhi2(g3.x, g3.y);  xl[4*ks+3] = packlo2(g3.x, g3.y);
        }
    }
    // wg hi -> B0, lo -> B1 (16 rows x 512B = 512 uint4 each)
    {
        const uint4* Wh = (const uint4*)g_wghi;
        const uint4* Wl = (const uint4*)g_wglo;
        #pragma unroll
        for (int i = 0; i < 4; i++) {
            int u = i * NT + tid;
            int row = u >> 5, c = u & 31;
            int o = row * 512 + ((c ^ (row & 7)) << 4);
            *(uint4*)(smem + S_B0 + o) = Wh[u];
            *(uint4*)(smem + S_B1 + o) = Wl[u];
        }
    }
    // x row norms (threads 0..63)
    if (tid < RT) {
        const float4* xr = (const float4*)&x[(size_t)(rb + tid) * DD];
        float s = 0.f;
        #pragma unroll 8
        for (int j = 0; j < 64; j++) {
            float4 v = xr[j];
            s = fmaf(v.x, v.x, fmaf(v.y, v.y, fmaf(v.z, v.z, fmaf(v.w, v.w, s))));
        }
        g_xn[rb + tid] = sqrtf(s);
    }
    __syncthreads();

    // ---- gate GEMM: N=16 per warp, 3-term, A from registers ----
    {
        float accg[2][4] = {};
        uint32_t bh[4], bl[4];
        #pragma unroll
        for (int ks = 0; ks < 16; ks++) {
            ldsm4(bh, addrB(sb + S_B0, 0, 2 * ks, 512, lane));
            ldsm4(bl, addrB(sb + S_B1, 0, 2 * ks, 512, lane));
            const uint32_t* ah = xh + 4 * ks;
            const uint32_t* al = xl + 4 * ks;
            mma_bf16(accg[0], ah, bh); mma_bf16(accg[1], ah, bh + 2);
            mma_bf16(accg[0], al, bh); mma_bf16(accg[1], al, bh + 2);
            mma_bf16(accg[0], ah, bl); mma_bf16(accg[1], ah, bl + 2);
        }
        #pragma unroll
        for (int t = 0; t < 2; t++) {
            float zA0 = accg[t][0] + bg[8*t + 2*tig];
            float zA1 = accg[t][1] + bg[8*t + 2*tig + 1];
            float zB0 = accg[t][2] + bg[8*t + 2*tig];
            float zB1 = accg[t][3] + bg[8*t + 2*tig + 1];
            *(float2*)&out[O_G + (size_t)(rb + rowA) * EE + 8*t + 2*tig] =
                make_float2(1.f/(1.f+__expf(-zA0)), 1.f/(1.f+__expf(-zA1)));
            *(float2*)&out[O_G + (size_t)(rb + rowB) * EE + 8*t + 2*tig] =
                make_float2(1.f/(1.f+__expf(-zB0)), 1.f/(1.f+__expf(-zB1)));
        }
    }
    __syncthreads();   // wg reads done -> buffer reusable

    // prefetch K[0]
    {
        const uint4* Kh = (const uint4*)g_Khi;
        const uint4* Kl = (const uint4*)g_Klo;
        #pragma unroll
        for (int i = 0; i < 16; i++) {
            int u = i * NT + tid;
            int row = u >> 5, c = u & 31;
            uint32_t o = (uint32_t)(row * 512 + ((c ^ (row & 7)) << 4));
            cpasync16(sb + S_B0 + o, Kh + u);
            cpasync16(sb + S_B1 + o, Kl + u);
        }
        CP_COMMIT();
    }

    for (int e = 0; e < EE; e++) {
        CP_WAIT0();
        __syncthreads();        // (1) K(e) resident

        // ======== GEMM1: logits[16 rows x 64 cols per warp], A in regs ========
        float acc[8][4] = {};
        {
            uint32_t bh[4], bl[4];
            #pragma unroll
            for (int ks = 0; ks < 16; ks++) {
                const uint32_t* ah = xh + 4 * ks;
                const uint32_t* al = xl + 4 * ks;
                #pragma unroll
                for (int p = 0; p < 4; p++) {
                    ldsm4(bh, addrB(sb + S_B0, 16 * p, 2 * ks, 512, lane));
                    ldsm4(bl, addrB(sb + S_B1, 16 * p, 2 * ks, 512, lane));
                    mma_bf16(acc[2*p],   ah, bh); mma_bf16(acc[2*p+1], ah, bh + 2);
                    mma_bf16(acc[2*p],   al, bh); mma_bf16(acc[2*p+1], al, bh + 2);
                    mma_bf16(acc[2*p],   ah, bl); mma_bf16(acc[2*p+1], ah, bl + 2);
                }
            }
        }
        __syncthreads();        // (2) K reads done -> V load into same buffer

        {
            const uint4* Vh = (const uint4*)g_Vthi + e * 2048;
            const uint4* Vl = (const uint4*)g_Vtlo + e * 2048;
            #pragma unroll
            for (int i = 0; i < 16; i++) {
                int u = i * NT + tid;
                int row = u >> 3, c = u & 7;
                uint32_t o = (uint32_t)(row * 128 + ((c ^ (row & 7)) << 4));
                cpasync16(sb + S_B0 + o, Vh + u);
                cpasync16(sb + S_B1 + o, Vl + u);
            }
            CP_COMMIT();
        }

        // ======== softmax (full row in-warp; logits ~N(0,1/16): no max-sub) ========
        uint32_t aH[16], aL[16];
        {
            float sA = 0.f, sB = 0.f;
            #pragma unroll
            for (int t = 0; t < 8; t++) {
                acc[t][0] = __expf(acc[t][0] * 0.0625f); sA += acc[t][0];
                acc[t][1] = __expf(acc[t][1] * 0.0625f); sA += acc[t][1];
                acc[t][2] = __expf(acc[t][2] * 0.0625f); sB += acc[t][2];
                acc[t][3] = __expf(acc[t][3] * 0.0625f); sB += acc[t][3];
            }
            sA += __shfl_xor_sync(0xffffffffu, sA, 1);
            sA += __shfl_xor_sync(0xffffffffu, sA, 2);
            sB += __shfl_xor_sync(0xffffffffu, sB, 1);
            sB += __shfl_xor_sync(0xffffffffu, sB, 2);
            float iA = 1.f / sA, iB = 1.f / sB;
            float* oaA = &out[O_A + ((size_t)(rb + rowA) * EE + e) * MM];
            float* oaB = &out[O_A + ((size_t)(rb + rowB) * EE + e) * MM];
            #pragma unroll
            for (int t = 0; t < 8; t++) {
                float a0 = acc[t][0] * iA, a1 = acc[t][1] * iA;
                float b0 = acc[t][2] * iB, b1 = acc[t][3] * iB;
                *(float2*)&oaA[8*t + 2*tig] = make_float2(a0, a1);
                *(float2*)&oaB[8*t + 2*tig] = make_float2(b0, b1);
                acc[t][0] = a0; acc[t][1] = a1; acc[t][2] = b0; acc[t][3] = b1;
            }
            #pragma unroll
            for (int ks = 0; ks < 4; ks++) {
                aH[4*ks+0] = packhi2(acc[2*ks][0],   acc[2*ks][1]);
                aH[4*ks+1] = packhi2(acc[2*ks][2],   acc[2*ks][3]);
                aH[4*ks+2] = packhi2(acc[2*ks+1][0], acc[2*ks+1][1]);
                aH[4*ks+3] = packhi2(acc[2*ks+1][2], acc[2*ks+1][3]);
                aL[4*ks+0] = packlo2(acc[2*ks][0],   acc[2*ks][1]);
                aL[4*ks+1] = packlo2(acc[2*ks][2],   acc[2*ks][3]);
                aL[4*ks+2] = packlo2(acc[2*ks+1][0], acc[2*ks+1][1]);
                aL[4*ks+3] = packlo2(acc[2*ks+1][2], acc[2*ks+1][3]);
            }
        }
        CP_WAIT0();
        __syncthreads();        // (3) V resident

        // ======== GEMM2: y[16 rows x 256 cols], A in regs; x reconstructed from regs ========
        float pxA = 0.f, pnA = 0.f, pxB = 0.f, pnB = 0.f;
        float* oyA = &out[O_Y + ((size_t)(rb + rowA) * EE + e) * DD];
        float* oyB = &out[O_Y + ((size_t)(rb + rowB) * EE + e) * DD];
        #pragma unroll
        for (int ch = 0; ch < 16; ch++) {
            float acc2[2][4] = {};
            {
                uint32_t bh[4], bl[4];
                #pragma unroll
                for (int ks = 0; ks < 4; ks++) {
                    ldsm4(bh, addrB(sb + S_B0, 16 * ch, 2 * ks, 128, lane));
                    ldsm4(bl, addrB(sb + S_B1, 16 * ch, 2 * ks, 128, lane));
                    const uint32_t* ah = aH + 4 * ks;
                    const uint32_t* al = aL + 4 * ks;
                    mma_bf16(acc2[0], ah, bh); mma_bf16(acc2[1], ah, bh + 2);
                    mma_bf16(acc2[0], al, bh); mma_bf16(acc2[1], al, bh + 2);
                    mma_bf16(acc2[0], ah, bl); mma_bf16(acc2[1], ah, bl + 2);
                }
            }
            #pragma unroll
            for (int j = 0; j < 2; j++) {
                int d = 16 * ch + 8 * j + 2 * tig;
                float y0 = acc2[j][0], y1 = acc2[j][1];
                float z0 = acc2[j][2], z1 = acc2[j][3];
                *(float2*)&oyA[d] = make_float2(y0, y1);
                *(float2*)&oyB[d] = make_float2(z0, z1);
                // x from persistent fragments (exact hi+lo reconstruction)
                uint32_t uhA = xh[4*ch + 2*j + 0], ulA = xl[4*ch + 2*j + 0];
                uint32_t uhB = xh[4*ch + 2*j + 1], ulB = xl[4*ch + 2*j + 1];
                float xA0 = b2f_lo(uhA) + b2f_lo(ulA), xA1 = b2f_hi(uhA) + b2f_hi(ulA);
                float xB0 = b2f_lo(uhB) + b2f_lo(ulB), xB1 = b2f_hi(uhB) + b2f_hi(ulB);
                pxA = fmaf(xA0, y0, fmaf(xA1, y1, pxA));
                pnA = fmaf(y0, y0, fmaf(y1, y1, pnA));
                pxB = fmaf(xB0, z0, fmaf(xB1, z1, pxB));
                pnB = fmaf(z0, z0, fmaf(z1, z1, pnB));
            }
        }
        __syncthreads();        // (4) V reads done -> K(e+1) prefetch safe

        if (e + 1 < EE) {
            const uint4* Kh = (const uint4*)g_Khi + (e + 1) * 2048;
            const uint4* Kl = (const uint4*)g_Klo + (e + 1) * 2048;
            #pragma unroll
            for (int i = 0; i < 16; i++) {
                int u = i * NT + tid;
                int row = u >> 5, c = u & 31;
                uint32_t o = (uint32_t)(row * 512 + ((c ^ (row & 7)) << 4));
                cpasync16(sb + S_B0 + o, Kh + u);
                cpasync16(sb + S_B1 + o, Kl + u);
            }
            CP_COMMIT();
        }

        // px/pn reduce + store (overlaps K prefetch)
        pxA += __shfl_xor_sync(0xffffffffu, pxA, 1);
        pxA += __shfl_xor_sync(0xffffffffu, pxA, 2);
        pnA += __shfl_xor_sync(0xffffffffu, pnA, 1);
        pnA += __shfl_xor_sync(0xffffffffu, pnA, 2);
        pxB += __shfl_xor_sync(0xffffffffu, pxB, 1);
        pxB += __shfl_xor_sync(0xffffffffu, pxB, 2);
        pnB += __shfl_xor_sync(0xffffffffu, pnB, 1);
        pnB += __shfl_xor_sync(0xffffffffu, pnB, 2);
        if (tig == 0) {
            g_px[(size_t)(rb + rowA) * EE + e] = pxA;
            g_pn[(size_t)(rb + rowA) * EE + e] = pnA;
            g_px[(size_t)(rb + rowB) * EE + e] = pxB;
            g_pn[(size_t)(rb + rowB) * EE + e] = pnB;
        }
    }
}

// ================= finisher: familiarity + argmax =================
__global__ __launch_bounds__(256) void more_fin(float* __restrict__ out) {
    int r = blockIdx.x * 256 + threadIdx.x;
    if (r >= BB) return;
    float xn = g_xn[r];
    float bestf = -INFINITY;
    int beste = 0;
    const float* gp = &out[O_G + (size_t)r * EE];
    #pragma unroll
    for (int e = 0; e < EE; e++) {
        float px = g_px[(size_t)r * EE + e];
        float pn = g_pn[(size_t)r * EE + e];
        float cosv = px / (xn * sqrtf(pn) + 1e-8f);
        float f = gp[e] * cosv;
        if (f > bestf) { bestf = f; beste = e; }
    }
    out[O_W + r] = (float)beste;
    out[O_S + r] = bestf;
}

extern "C" void kernel_launch(void* const* d_in, const int* in_sizes, int n_in,
                              void* d_out, int out_size) {
    (void)in_sizes; (void)n_in; (void)out_size;
    const float* x  = (const float*)d_in[0];
    const float* K  = (const float*)d_in[1];
    const float* V  = (const float*)d_in[2];
    const float* wg = (const float*)d_in[3];
    const float* bg = (const float*)d_in[4];
    float* out = (float*)d_out;

    pp_kernel<<<256, 256>>>(K, V, wg);

    cudaFuncSetAttribute(more_mma, cudaFuncAttributeMaxDynamicSharedMemorySize, SMEM_REQ);
    more_mma<<<BB / RT, NT, SMEM_REQ>>>(x, bg, out);

    more_fin<<<BB / 256, 256>>>(out);
}